// round 6
// baseline (speedup 1.0000x reference)
#include <cuda_runtime.h>
#include <cstdint>

#define Bb 32
#define Nn 1024
#define Dd 512
#define Kk 64
#define KC 80            // K + G clusters
#define ROWS (Bb * Nn)   // 32768

// g_assign TRANSPOSED: [b][k][n]  (b*Kk + k)*Nn + n, tf32-pre-rounded
__device__ __align__(16) float g_assign[ROWS * Kk];
__device__ float g_asum_part[256 * Kk];
__device__ float g_ssq_part[Bb * 8];
// W pre-rounded + padded per chunk in the exact smem image [16][32][88]
__device__ __align__(16) float g_Wt[16 * 32 * 88];

// ---------------------------------------------------------------------------
__device__ __forceinline__ float to_tf32(float x) {
    uint32_t r;
    asm("cvt.rna.tf32.f32 %0, %1;" : "=r"(r) : "f"(x));
    return __uint_as_float(r);
}

__device__ __forceinline__ void mma8(float* d, const uint32_t* a,
                                     uint32_t b0, uint32_t b1) {
    asm volatile(
        "mma.sync.aligned.m16n8k8.row.col.f32.tf32.tf32.f32 "
        "{%0,%1,%2,%3}, {%4,%5,%6,%7}, {%8,%9}, {%0,%1,%2,%3};"
        : "+f"(d[0]), "+f"(d[1]), "+f"(d[2]), "+f"(d[3])
        : "r"(a[0]), "r"(a[1]), "r"(a[2]), "r"(a[3]), "r"(b0), "r"(b1));
}

__device__ __forceinline__ void cp16(void* sdst, const void* gsrc) {
    uint32_t s = (uint32_t)__cvta_generic_to_shared(sdst);
    asm volatile("cp.async.cg.shared.global [%0], [%1], 16;" :: "r"(s), "l"(gsrc));
}
__device__ __forceinline__ void cp_commit() { asm volatile("cp.async.commit_group;"); }
__device__ __forceinline__ void cp_wait0()  { asm volatile("cp.async.wait_group 0;"); }

// ---------------------------------------------------------------------------
// prep: g_Wt[c][r][col] = tf32(W[(c*32+r)*80 + col]) for col<80, 0 pad to 88
// ---------------------------------------------------------------------------
__global__ void prep_wt(const float* __restrict__ W)
{
    int i = blockIdx.x * blockDim.x + threadIdx.x;
    if (i >= 16 * 32 * 88) return;
    int c   = i / 2816;
    int rem = i % 2816;
    int r   = rem / 88;
    int col = rem % 88;
    g_Wt[i] = (col < KC) ? to_tf32(W[(size_t)(c * 32 + r) * KC + col]) : 0.f;
}

// ---------------------------------------------------------------------------
// Kernel A: logits = x @ clusters ; BN ; softmax(80) ; keep 64 (transposed out)
// Block 128x80, 8 warps (4Mx2N), warp 32x40.
// A: 2-chunk-deep LDG register prefetch. B: cp.async from g_Wt, 1 chunk ahead.
// One __syncthreads per chunk.
// Dynamic smem (floats): As[2][128][36]=9216, Bs[2][32][88]=5632  (59392 B)
// softmax overlay: Ls[128][81] @0, inv @10368, red @10496
// ---------------------------------------------------------------------------
#define ASSIGN_SMEM_BYTES 59392

__global__ __launch_bounds__(256, 2) void assign_kernel(
    const float* __restrict__ x,
    const float* __restrict__ bnw, const float* __restrict__ bnb,
    const float* __restrict__ bnm, const float* __restrict__ bnv)
{
    extern __shared__ float dyn[];
    float* AsBase = dyn;                 // [2][128][36]
    float* BsBase = dyn + 9216;          // [2][32][88]
    float (*Ls)[81] = reinterpret_cast<float(*)[81]>(dyn);
    float* invp = dyn + 10368;
    float* redp = dyn + 10496;
    __shared__ float s_sc[KC], s_tc[KC];

    const int t = threadIdx.x;
    const int lane = t & 31;
    const int wid = t >> 5;
    const int warpM = wid & 3;
    const int warpN = wid >> 2;
    const int g   = lane >> 2;
    const int tig = lane & 3;
    const int row0 = blockIdx.x * 128;

    if (t < KC) {
        float iv = rsqrtf(bnv[t] + 1e-5f);
        float sc = bnw[t] * iv;
        s_sc[t] = sc;
        s_tc[t] = bnb[t] - bnm[t] * sc;
    }

    float acc[2][5][4];
#pragma unroll
    for (int a = 0; a < 2; a++)
#pragma unroll
        for (int b = 0; b < 5; b++)
#pragma unroll
            for (int c = 0; c < 4; c++) acc[a][b][c] = 0.f;

    const int ar = t >> 3, ac4 = (t & 7) << 2;

    // prologue: B(0) via cp.async; A(0), A(1) via LDG
    {
#pragma unroll
        for (int j = 0; j < 3; j++) {
            int i = t + j * 256;
            if (i < 704) cp16((char*)BsBase + i * 16, (const char*)g_Wt + i * 16);
        }
        cp_commit();
    }
    float4 pa[2][4];
#pragma unroll
    for (int j = 0; j < 4; j++) {
        pa[0][j] = *reinterpret_cast<const float4*>(
            &x[(size_t)(row0 + ar + j * 32) * Dd + ac4]);
        pa[1][j] = *reinterpret_cast<const float4*>(
            &x[(size_t)(row0 + ar + j * 32) * Dd + 32 + ac4]);
    }

    for (int c = 0; c < 16; c++) {
        const int p = c & 1;
        float* As = AsBase + p * (128 * 36);
        float* Bs = BsBase + p * (32 * 88);

        // STS A(c) with tf32 round
#pragma unroll
        for (int j = 0; j < 4; j++) {
            float* dst = As + (ar + j * 32) * 36 + ac4;
            dst[0] = to_tf32(pa[p][j].x); dst[1] = to_tf32(pa[p][j].y);
            dst[2] = to_tf32(pa[p][j].z); dst[3] = to_tf32(pa[p][j].w);
        }
        // LDG A(c+2) into the slot just consumed
        if (c < 14) {
            const int kt = (c + 2) * 32;
#pragma unroll
            for (int j = 0; j < 4; j++)
                pa[p][j] = *reinterpret_cast<const float4*>(
                    &x[(size_t)(row0 + ar + j * 32) * Dd + kt + ac4]);
        }

        cp_wait0();          // B(c) resident (only outstanding group)
        __syncthreads();     // also frees Bs[1-p] and As[p] for writes below

        // B(c+1) into the buffer freed by MMA(c-1)
        if (c < 15) {
            const char* src = (const char*)g_Wt + (size_t)(c + 1) * 11264;
            char* dstB = (char*)BsBase + (1 - p) * 11264;
#pragma unroll
            for (int j = 0; j < 3; j++) {
                int i = t + j * 256;
                if (i < 704) cp16(dstB + i * 16, src + i * 16);
            }
            cp_commit();
        }

        // MMA phase
#pragma unroll
        for (int ks = 0; ks < 4; ks++) {
            const int kk = ks << 3;
            uint32_t af[2][4];
#pragma unroll
            for (int mf = 0; mf < 2; mf++) {
                const int rb = warpM * 32 + mf * 16 + g;
                af[mf][0] = __float_as_uint(As[(rb    ) * 36 + kk + tig    ]);
                af[mf][1] = __float_as_uint(As[(rb + 8) * 36 + kk + tig    ]);
                af[mf][2] = __float_as_uint(As[(rb    ) * 36 + kk + tig + 4]);
                af[mf][3] = __float_as_uint(As[(rb + 8) * 36 + kk + tig + 4]);
            }
#pragma unroll
            for (int nf = 0; nf < 5; nf++) {
                const int cb = warpN * 40 + nf * 8 + g;
                uint32_t b0 = __float_as_uint(Bs[(kk + tig    ) * 88 + cb]);
                uint32_t b1 = __float_as_uint(Bs[(kk + tig + 4) * 88 + cb]);
                mma8(acc[0][nf], af[0], b0, b1);
                mma8(acc[1][nf], af[1], b0, b1);
            }
        }
    }
    __syncthreads();   // buffers dead; softmax overlay begins

    // BN fold + stage logits
#pragma unroll
    for (int mf = 0; mf < 2; mf++)
#pragma unroll
        for (int nf = 0; nf < 5; nf++)
#pragma unroll
            for (int c = 0; c < 4; c++) {
                int row = warpM * 32 + mf * 16 + g + ((c >> 1) << 3);
                int col = warpN * 40 + nf * 8 + 2 * tig + (c & 1);
                Ls[row][col] = fmaf(acc[mf][nf][c], s_sc[col], s_tc[col]);
            }
    __syncthreads();

    if (t < 128) {
        float m = -1e30f;
#pragma unroll
        for (int j = 0; j < KC; j++) m = fmaxf(m, Ls[t][j]);
        float ssum = 0.f;
#pragma unroll
        for (int j = 0; j < KC; j++) {
            float e = __expf(Ls[t][j] - m);
            ssum += e;
            if (j < Kk) Ls[t][j] = e;
        }
        invp[t] = 1.f / ssum;
    }
    __syncthreads();

    // transposed, tf32-rounded store: g_assign[(b*64+k)*1024 + n]
    const int bidx = row0 >> 10;
    const int nbase = row0 & 1023;
#pragma unroll
    for (int i = t; i < 128 * Kk; i += 256) {
        int k = i >> 7, r = i & 127;
        float e = Ls[r][k] * invp[r];
        g_assign[((size_t)bidx * Kk + k) * Nn + nbase + r] = to_tf32(e);
    }

    // per-column partial sums (k fixed per thread)
    float partial = 0.f;
#pragma unroll
    for (int i = t; i < 128 * Kk; i += 256) {
        int r = i >> 6, k = i & 63;
        partial += Ls[r][k] * invp[r];
    }
    redp[t] = partial;
    __syncthreads();
    if (t < 64)
        g_asum_part[blockIdx.x * Kk + t] =
            redp[t] + redp[t + 64] + redp[t + 128] + redp[t + 192];
}

// ---------------------------------------------------------------------------
// Kernel B: O[k][d] = sum_n aT[k,n]*x[n,d] - asum[k]*c2[d,k]
// 128 threads, 4 warps (2Mk x 2Nd), warp 32x32.
// x: 2-deep LDG register prefetch; aT: cp.async 1 chunk ahead (L2-hot).
// One __syncthreads per chunk.
// ---------------------------------------------------------------------------
__global__ __launch_bounds__(128, 4) void vlad_kernel(
    const float* __restrict__ x,
    const float* __restrict__ c2,
    float* __restrict__ out)
{
    __shared__ float aT_s[2][64][36];
    __shared__ float x_s[2][32][72];
    __shared__ float asum_s[64];
    __shared__ float redsq[4];

    const int t = threadIdx.x;
    const int lane = t & 31;
    const int wid = t >> 5;
    const int warpM = wid & 1;
    const int warpN = wid >> 1;
    const int g   = lane >> 2;
    const int tig = lane & 3;
    const int b  = blockIdx.y;
    const int d0 = blockIdx.x * 64;

    if (t < 64) {
        float s = 0.f;
#pragma unroll
        for (int j = 0; j < 8; j++)
            s += g_asum_part[((b << 3) + j) * Kk + t];
        asum_s[t] = s;
    }

    float acc[2][4][4];
#pragma unroll
    for (int mf = 0; mf < 2; mf++)
#pragma unroll
        for (int nf = 0; nf < 4; nf++)
#pragma unroll
            for (int c = 0; c < 4; c++) acc[mf][nf][c] = 0.f;

    const float* xb  = x + (size_t)b * Nn * Dd + d0;
    const float* abT = g_assign + (size_t)b * Kk * Nn;

    const int xn = t >> 4, xq = (t & 15) << 2;
    float4 px[2][4];

    // prologue: a(0) via cp.async; x(0), x(1) via LDG
#pragma unroll
    for (int j = 0; j < 4; j++) {
        int i = t + j * 128;
        int k = i >> 3, seg = i & 7;
        cp16(&aT_s[0][k][seg << 2], abT + (size_t)k * Nn + (seg << 2));
    }
    cp_commit();
#pragma unroll
    for (int j = 0; j < 4; j++) {
        px[0][j] = *reinterpret_cast<const float4*>(
            &xb[(size_t)(xn + j * 8) * Dd + xq]);
        px[1][j] = *reinterpret_cast<const float4*>(
            &xb[(size_t)(32 + xn + j * 8) * Dd + xq]);
    }

    for (int c = 0; c < 32; c++) {
        const int p = c & 1;

        // STS x(c)
#pragma unroll
        for (int j = 0; j < 4; j++) {
            float* dst = &x_s[p][xn + j * 8][xq];
            dst[0] = to_tf32(px[p][j].x); dst[1] = to_tf32(px[p][j].y);
            dst[2] = to_tf32(px[p][j].z); dst[3] = to_tf32(px[p][j].w);
        }
        // LDG x(c+2)
        if (c < 30) {
            const int n2 = (c + 2) * 32;
#pragma unroll
            for (int j = 0; j < 4; j++)
                px[p][j] = *reinterpret_cast<const float4*>(
                    &xb[(size_t)(n2 + xn + j * 8) * Dd + xq]);
        }

        cp_wait0();          // a(c) resident
        __syncthreads();

        // a(c+1) into freed buffer
        if (c < 31) {
            const int n1 = (c + 1) * 32;
#pragma unroll
            for (int j = 0; j < 4; j++) {
                int i = t + j * 128;
                int k = i >> 3, seg = i & 7;
                cp16(&aT_s[1 - p][k][seg << 2],
                     abT + (size_t)k * Nn + n1 + (seg << 2));
            }
            cp_commit();
        }

        // MMA phase
#pragma unroll
        for (int ks = 0; ks < 4; ks++) {
            const int kk = ks << 3;
            uint32_t af[2][4];
#pragma unroll
            for (int mf = 0; mf < 2; mf++) {
                const int rb = warpM * 32 + mf * 16 + g;
                af[mf][0] = __float_as_uint(aT_s[p][rb    ][kk + tig    ]);
                af[mf][1] = __float_as_uint(aT_s[p][rb + 8][kk + tig    ]);
                af[mf][2] = __float_as_uint(aT_s[p][rb    ][kk + tig + 4]);
                af[mf][3] = __float_as_uint(aT_s[p][rb + 8][kk + tig + 4]);
            }
#pragma unroll
            for (int nf = 0; nf < 4; nf++) {
                const int cb = warpN * 32 + nf * 8 + g;
                uint32_t b0 = __float_as_uint(x_s[p][kk + tig    ][cb]);
                uint32_t b1 = __float_as_uint(x_s[p][kk + tig + 4][cb]);
                mma8(acc[0][nf], af[0], b0, b1);
                mma8(acc[1][nf], af[1], b0, b1);
            }
        }
    }

    // epilogue
    float* ob = out + (size_t)b * (Dd * Kk);
    float ssq = 0.f;
#pragma unroll
    for (int mf = 0; mf < 2; mf++)
#pragma unroll
        for (int nf = 0; nf < 4; nf++)
#pragma unroll
            for (int c = 0; c < 4; c++) {
                int k = warpM * 32 + mf * 16 + g + ((c >> 1) << 3);
                int d = d0 + warpN * 32 + nf * 8 + 2 * tig + (c & 1);
                float v = acc[mf][nf][c] - asum_s[k] * c2[(size_t)d * Kk + k];
                ob[(size_t)d * Kk + k] = v;
                ssq = fmaf(v, v, ssq);
            }
#pragma unroll
    for (int off = 16; off > 0; off >>= 1)
        ssq += __shfl_xor_sync(0xffffffffu, ssq, off);
    if (lane == 0) redsq[wid] = ssq;
    __syncthreads();
    if (t == 0)
        g_ssq_part[b * 8 + blockIdx.x] = redsq[0] + redsq[1] + redsq[2] + redsq[3];
}

// ---------------------------------------------------------------------------
// Kernel C: pure scale pass (composed double L2-normalize)
// ---------------------------------------------------------------------------
__global__ __launch_bounds__(1024) void norm_kernel(float* __restrict__ out)
{
    const int b = blockIdx.x;
    const int t = threadIdx.x;
    __shared__ float scale_s;

    if (t == 0) {
        float v = 0.f;
#pragma unroll
        for (int j = 0; j < 8; j++) v += g_ssq_part[b * 8 + j];
        float s1 = v + 1e-12f;
        float n1 = sqrtf(s1);
        float s2 = v / s1 + 1e-12f;
        scale_s = 1.f / (n1 * sqrtf(s2));
    }
    __syncthreads();

    float sc = scale_s;
    float4* p = reinterpret_cast<float4*>(out + (size_t)b * (Dd * Kk));
#pragma unroll 4
    for (int i = t; i < 8192; i += 1024) {
        float4 v = p[i];
        v.x *= sc; v.y *= sc; v.z *= sc; v.w *= sc;
        p[i] = v;
    }
}

// ---------------------------------------------------------------------------
extern "C" void kernel_launch(void* const* d_in, const int* in_sizes, int n_in,
                              void* d_out, int out_size)
{
    const float* x   = (const float*)d_in[0];
    const float* W   = (const float*)d_in[1];
    const float* c2  = (const float*)d_in[2];
    const float* bnw = (const float*)d_in[3];
    const float* bnb = (const float*)d_in[4];
    const float* bnm = (const float*)d_in[5];
    const float* bnv = (const float*)d_in[6];
    float* out = (float*)d_out;

    cudaFuncSetAttribute(assign_kernel,
                         cudaFuncAttributeMaxDynamicSharedMemorySize,
                         ASSIGN_SMEM_BYTES);

    prep_wt<<<176, 256>>>(W);
    assign_kernel<<<ROWS / 128, 256, ASSIGN_SMEM_BYTES>>>(x, bnw, bnb, bnm, bnv);
    vlad_kernel<<<dim3(Dd / 64, Bb), 128>>>(x, c2, out);
    norm_kernel<<<Bb, 1024>>>(out);
}

// round 7
// speedup vs baseline: 1.2340x; 1.2340x over previous
#include <cuda_runtime.h>
#include <cstdint>

#define Bb 32
#define Nn 1024
#define Dd 512
#define Kk 64
#define KC 80            // K + G clusters
#define ROWS (Bb * Nn)   // 32768

// g_assign stored TRANSPOSED: [b][k][n]  (b*Kk + k)*Nn + n, tf32-pre-rounded
__device__ __align__(16) float g_assign[ROWS * Kk];
__device__ float g_asum_part[256 * Kk];
__device__ float g_ssq_part[Bb * 8];

// ---------------------------------------------------------------------------
__device__ __forceinline__ float to_tf32(float x) {
    uint32_t r;
    asm("cvt.rna.tf32.f32 %0, %1;" : "=r"(r) : "f"(x));
    return __uint_as_float(r);
}

__device__ __forceinline__ void mma8(float* d, const uint32_t* a,
                                     uint32_t b0, uint32_t b1) {
    asm volatile(
        "mma.sync.aligned.m16n8k8.row.col.f32.tf32.tf32.f32 "
        "{%0,%1,%2,%3}, {%4,%5,%6,%7}, {%8,%9}, {%0,%1,%2,%3};"
        : "+f"(d[0]), "+f"(d[1]), "+f"(d[2]), "+f"(d[3])
        : "r"(a[0]), "r"(a[1]), "r"(a[2]), "r"(a[3]), "r"(b0), "r"(b1));
}

__device__ __forceinline__ void cp16(void* sdst, const void* gsrc) {
    uint32_t s = (uint32_t)__cvta_generic_to_shared(sdst);
    asm volatile("cp.async.cg.shared.global [%0], [%1], 16;" :: "r"(s), "l"(gsrc));
}
__device__ __forceinline__ void cp_commit() {
    asm volatile("cp.async.commit_group;");
}
__device__ __forceinline__ void cp_wait0() {
    asm volatile("cp.async.wait_group 0;");
}

// ---------------------------------------------------------------------------
// Kernel A: logits = x @ clusters ; BN ; softmax(80) ; keep 64 (transposed out)
// Block 128x80, 8 warps (4Mx2N), warp 32x40. Double-buffered smem, one
// __syncthreads per chunk, register prefetch of next chunk.   (round-4 exact)
// ---------------------------------------------------------------------------
#define ASSIGN_SMEM_BYTES 59392

__global__ __launch_bounds__(256, 2) void assign_kernel(
    const float* __restrict__ x,      // [32768, 512]
    const float* __restrict__ W,      // [512, 80]
    const float* __restrict__ bnw, const float* __restrict__ bnb,
    const float* __restrict__ bnm, const float* __restrict__ bnv)
{
    extern __shared__ float dyn[];
    float* AsBase = dyn;                 // [2][128][36]
    float* BsBase = dyn + 9216;          // [2][32][88]
    float (*Ls)[81] = reinterpret_cast<float(*)[81]>(dyn);
    float* invp = dyn + 10368;
    float* redp = dyn + 10496;
    __shared__ float s_sc[KC], s_tc[KC];

    const int t = threadIdx.x;
    const int lane = t & 31;
    const int wid = t >> 5;
    const int warpM = wid & 3;
    const int warpN = wid >> 2;
    const int g   = lane >> 2;
    const int tig = lane & 3;
    const int row0 = blockIdx.x * 128;

    if (t < KC) {
        float iv = rsqrtf(bnv[t] + 1e-5f);
        float sc = bnw[t] * iv;
        s_sc[t] = sc;
        s_tc[t] = bnb[t] - bnm[t] * sc;
    }

    float acc[2][5][4];
#pragma unroll
    for (int a = 0; a < 2; a++)
#pragma unroll
        for (int b = 0; b < 5; b++)
#pragma unroll
            for (int c = 0; c < 4; c++) acc[a][b][c] = 0.f;

    float4 pa[4];
    float4 pb[3];
    const int ar = t >> 3, ac4 = (t & 7) << 2;

    // prologue: LDG chunk 0
#pragma unroll
    for (int j = 0; j < 4; j++)
        pa[j] = *reinterpret_cast<const float4*>(
            &x[(size_t)(row0 + ar + j * 32) * Dd + ac4]);
#pragma unroll
    for (int j = 0; j < 3; j++) {
        int i = t + j * 256;
        if (i < 640)
            pb[j] = *reinterpret_cast<const float4*>(
                &W[(size_t)(i / 20) * KC + ((i % 20) << 2)]);
    }

    for (int c = 0; c < 16; c++) {
        const int p = c & 1;
        float* As = AsBase + p * (128 * 36);
        float* Bs = BsBase + p * (32 * 88);

        // STS current chunk (tf32 round)
#pragma unroll
        for (int j = 0; j < 4; j++) {
            float* dst = As + (ar + j * 32) * 36 + ac4;
            dst[0] = to_tf32(pa[j].x); dst[1] = to_tf32(pa[j].y);
            dst[2] = to_tf32(pa[j].z); dst[3] = to_tf32(pa[j].w);
        }
#pragma unroll
        for (int j = 0; j < 3; j++) {
            int i = t + j * 256;
            if (i < 640) {
                float* dst = Bs + (i / 20) * 88 + ((i % 20) << 2);
                dst[0] = to_tf32(pb[j].x); dst[1] = to_tf32(pb[j].y);
                dst[2] = to_tf32(pb[j].z); dst[3] = to_tf32(pb[j].w);
            }
        }
        __syncthreads();

        // LDG next chunk while MMAs run
        if (c < 15) {
            const int kt = (c + 1) * 32;
#pragma unroll
            for (int j = 0; j < 4; j++)
                pa[j] = *reinterpret_cast<const float4*>(
                    &x[(size_t)(row0 + ar + j * 32) * Dd + kt + ac4]);
#pragma unroll
            for (int j = 0; j < 3; j++) {
                int i = t + j * 256;
                if (i < 640)
                    pb[j] = *reinterpret_cast<const float4*>(
                        &W[(size_t)(kt + i / 20) * KC + ((i % 20) << 2)]);
            }
        }

        // MMA phase
#pragma unroll
        for (int ks = 0; ks < 4; ks++) {
            const int kk = ks << 3;
            uint32_t af[2][4];
#pragma unroll
            for (int mf = 0; mf < 2; mf++) {
                const int rb = warpM * 32 + mf * 16 + g;
                af[mf][0] = __float_as_uint(As[(rb    ) * 36 + kk + tig    ]);
                af[mf][1] = __float_as_uint(As[(rb + 8) * 36 + kk + tig    ]);
                af[mf][2] = __float_as_uint(As[(rb    ) * 36 + kk + tig + 4]);
                af[mf][3] = __float_as_uint(As[(rb + 8) * 36 + kk + tig + 4]);
            }
#pragma unroll
            for (int nf = 0; nf < 5; nf++) {
                const int cb = warpN * 40 + nf * 8 + g;
                uint32_t b0 = __float_as_uint(Bs[(kk + tig    ) * 88 + cb]);
                uint32_t b1 = __float_as_uint(Bs[(kk + tig + 4) * 88 + cb]);
                mma8(acc[0][nf], af[0], b0, b1);
                mma8(acc[1][nf], af[1], b0, b1);
            }
        }
    }
    __syncthreads();   // buffers dead; softmax overlay begins

    // BN fold + stage logits
#pragma unroll
    for (int mf = 0; mf < 2; mf++)
#pragma unroll
        for (int nf = 0; nf < 5; nf++)
#pragma unroll
            for (int c = 0; c < 4; c++) {
                int row = warpM * 32 + mf * 16 + g + ((c >> 1) << 3);
                int col = warpN * 40 + nf * 8 + 2 * tig + (c & 1);
                Ls[row][col] = fmaf(acc[mf][nf][c], s_sc[col], s_tc[col]);
            }
    __syncthreads();

    if (t < 128) {
        float m = -1e30f;
#pragma unroll
        for (int j = 0; j < KC; j++) m = fmaxf(m, Ls[t][j]);
        float ssum = 0.f;
#pragma unroll
        for (int j = 0; j < KC; j++) {
            float e = __expf(Ls[t][j] - m);
            ssum += e;
            if (j < Kk) Ls[t][j] = e;
        }
        invp[t] = 1.f / ssum;
    }
    __syncthreads();

    // transposed, tf32-rounded store: g_assign[(b*64+k)*1024 + n]
    const int bidx = row0 >> 10;       // batch
    const int nbase = row0 & 1023;
#pragma unroll
    for (int i = t; i < 128 * Kk; i += 256) {
        int k = i >> 7, r = i & 127;
        float e = Ls[r][k] * invp[r];
        g_assign[((size_t)bidx * Kk + k) * Nn + nbase + r] = to_tf32(e);
    }

    // per-column partial sums (k fixed per thread in this mapping)
    float partial = 0.f;
#pragma unroll
    for (int i = t; i < 128 * Kk; i += 256) {
        int r = i >> 6, k = i & 63;
        partial += Ls[r][k] * invp[r];
    }
    redp[t] = partial;
    __syncthreads();
    if (t < 64)
        g_asum_part[blockIdx.x * Kk + t] =
            redp[t] + redp[t + 64] + redp[t + 128] + redp[t + 192];
}

// ---------------------------------------------------------------------------
// Kernel B: O[k][d] = sum_n aT[k,n]*x[n,d] - asum[k]*c2[d,k]   (round-4 exact)
// ---------------------------------------------------------------------------
__global__ __launch_bounds__(128, 4) void vlad_kernel(
    const float* __restrict__ x,     // [32768, 512]
    const float* __restrict__ c2,    // [512, 64]
    float* __restrict__ out)         // [32, 512*64]
{
    __shared__ float aT_s[2][64][36];
    __shared__ float x_s[2][32][72];
    __shared__ float asum_s[64];
    __shared__ float redsq[4];

    const int t = threadIdx.x;
    const int lane = t & 31;
    const int wid = t >> 5;
    const int warpM = wid & 1;
    const int warpN = wid >> 1;
    const int g   = lane >> 2;
    const int tig = lane & 3;
    const int b  = blockIdx.y;
    const int d0 = blockIdx.x * 64;

    if (t < 64) {
        float s = 0.f;
#pragma unroll
        for (int j = 0; j < 8; j++)
            s += g_asum_part[((b << 3) + j) * Kk + t];
        asum_s[t] = s;
    }

    float acc[2][4][4];
#pragma unroll
    for (int mf = 0; mf < 2; mf++)
#pragma unroll
        for (int nf = 0; nf < 4; nf++)
#pragma unroll
            for (int c = 0; c < 4; c++) acc[mf][nf][c] = 0.f;

    const float* xb  = x + (size_t)b * Nn * Dd + d0;
    const float* abT = g_assign + (size_t)b * Kk * Nn;

    const int xn = t >> 4, xq = (t & 15) << 2;
    float4 px[4];

#pragma unroll
    for (int j = 0; j < 4; j++) {
        int i = t + j * 128;
        int k = i >> 3, seg = i & 7;
        cp16(&aT_s[0][k][seg << 2], abT + (size_t)k * Nn + (seg << 2));
    }
    cp_commit();
#pragma unroll
    for (int j = 0; j < 4; j++)
        px[j] = *reinterpret_cast<const float4*>(&xb[(size_t)(xn + j * 8) * Dd + xq]);

    for (int c = 0; c < 32; c++) {
        const int p = c & 1;

        cp_wait0();
#pragma unroll
        for (int j = 0; j < 4; j++) {
            float* dst = &x_s[p][xn + j * 8][xq];
            dst[0] = to_tf32(px[j].x); dst[1] = to_tf32(px[j].y);
            dst[2] = to_tf32(px[j].z); dst[3] = to_tf32(px[j].w);
        }
        __syncthreads();

        if (c < 31) {
            const int n1 = (c + 1) * 32;
#pragma unroll
            for (int j = 0; j < 4; j++) {
                int i = t + j * 128;
                int k = i >> 3, seg = i & 7;
                cp16(&aT_s[1 - p][k][seg << 2],
                     abT + (size_t)k * Nn + n1 + (seg << 2));
            }
            cp_commit();
#pragma unroll
            for (int j = 0; j < 4; j++)
                px[j] = *reinterpret_cast<const float4*>(
                    &xb[(size_t)(n1 + xn + j * 8) * Dd + xq]);
        }

#pragma unroll
        for (int ks = 0; ks < 4; ks++) {
            const int kk = ks << 3;
            uint32_t af[2][4];
#pragma unroll
            for (int mf = 0; mf < 2; mf++) {
                const int rb = warpM * 32 + mf * 16 + g;
                af[mf][0] = __float_as_uint(aT_s[p][rb    ][kk + tig    ]);
                af[mf][1] = __float_as_uint(aT_s[p][rb + 8][kk + tig    ]);
                af[mf][2] = __float_as_uint(aT_s[p][rb    ][kk + tig + 4]);
                af[mf][3] = __float_as_uint(aT_s[p][rb + 8][kk + tig + 4]);
            }
#pragma unroll
            for (int nf = 0; nf < 4; nf++) {
                const int cb = warpN * 32 + nf * 8 + g;
                uint32_t b0 = __float_as_uint(x_s[p][kk + tig    ][cb]);
                uint32_t b1 = __float_as_uint(x_s[p][kk + tig + 4][cb]);
                mma8(acc[0][nf], af[0], b0, b1);
                mma8(acc[1][nf], af[1], b0, b1);
            }
        }
    }

    float* ob = out + (size_t)b * (Dd * Kk);
    float ssq = 0.f;
#pragma unroll
    for (int mf = 0; mf < 2; mf++)
#pragma unroll
        for (int nf = 0; nf < 4; nf++)
#pragma unroll
            for (int c = 0; c < 4; c++) {
                int k = warpM * 32 + mf * 16 + g + ((c >> 1) << 3);
                int d = d0 + warpN * 32 + nf * 8 + 2 * tig + (c & 1);
                float v = acc[mf][nf][c] - asum_s[k] * c2[(size_t)d * Kk + k];
                ob[(size_t)d * Kk + k] = v;
                ssq = fmaf(v, v, ssq);
            }
#pragma unroll
    for (int off = 16; off > 0; off >>= 1)
        ssq += __shfl_xor_sync(0xffffffffu, ssq, off);
    if (lane == 0) redsq[wid] = ssq;
    __syncthreads();
    if (t == 0)
        g_ssq_part[b * 8 + blockIdx.x] = redsq[0] + redsq[1] + redsq[2] + redsq[3];
}

// ---------------------------------------------------------------------------
// Kernel C: pure scale pass, 8 blocks per batch (256 blocks total).
// Each block redundantly sums the 8 partials (identical order -> identical
// scale bitwise) and scales its 4096-float slice.
// ---------------------------------------------------------------------------
__global__ __launch_bounds__(256) void norm_kernel(float* __restrict__ out)
{
    const int b     = blockIdx.x >> 3;       // batch
    const int slice = blockIdx.x & 7;        // 0..7
    const int t = threadIdx.x;

    float v = 0.f;
#pragma unroll
    for (int j = 0; j < 8; j++) v += g_ssq_part[b * 8 + j];
    float s1 = v + 1e-12f;
    float n1 = sqrtf(s1);
    float s2 = v / s1 + 1e-12f;
    const float sc = 1.f / (n1 * sqrtf(s2));

    float4* p = reinterpret_cast<float4*>(out + (size_t)b * (Dd * Kk)) +
                slice * 1024;
#pragma unroll
    for (int i = t; i < 1024; i += 256) {
        float4 w = p[i];
        w.x *= sc; w.y *= sc; w.z *= sc; w.w *= sc;
        p[i] = w;
    }
}

// ---------------------------------------------------------------------------
extern "C" void kernel_launch(void* const* d_in, const int* in_sizes, int n_in,
                              void* d_out, int out_size)
{
    const float* x   = (const float*)d_in[0];
    const float* W   = (const float*)d_in[1];
    const float* c2  = (const float*)d_in[2];
    const float* bnw = (const float*)d_in[3];
    const float* bnb = (const float*)d_in[4];
    const float* bnm = (const float*)d_in[5];
    const float* bnv = (const float*)d_in[6];
    float* out = (float*)d_out;

    cudaFuncSetAttribute(assign_kernel,
                         cudaFuncAttributeMaxDynamicSharedMemorySize,
                         ASSIGN_SMEM_BYTES);

    assign_kernel<<<ROWS / 128, 256, ASSIGN_SMEM_BYTES>>>(x, W, bnw, bnb, bnm, bnv);
    vlad_kernel<<<dim3(Dd / 64, Bb), 128>>>(x, c2, out);
    norm_kernel<<<Bb * 8, 256>>>(out);
}